// round 2
// baseline (speedup 1.0000x reference)
#include <cuda_runtime.h>
#include <cstdint>

#define B_ 2
#define S_ 2048
#define D_ 1024
#define H_ 16
#define HD_ 64

// Scratch (allocation-free rule: device globals)
__device__ float g_qkv[3 * B_ * H_ * S_ * HD_];   // [which][b][h][s][hd]  48MB
__device__ float g_vals[B_ * S_ * D_];            // scrambled attn output 16MB

// ---------------------------------------------------------------------------
// Tiled SGEMM: C[M,N] = A[M,K] @ B[K,N] + bias, 128x128 tile, BK=16,
// 256 threads, 8x8 micro-tile per thread.
// MODE 0: A = x, epilogue scatters into g_qkv ([3][B][H][S][64] layout)
// MODE 1: A = g_vals, epilogue writes C row-major (d_out)
// ---------------------------------------------------------------------------
template <int MODE>
__global__ void __launch_bounds__(256) gemm128(
    const float* __restrict__ A, const float* __restrict__ Bm,
    const float* __restrict__ bias, float* __restrict__ C,
    int M, int N, int K)
{
    __shared__ float As[16][132];   // transposed A tile: As[k][m]
    __shared__ float Bs[16][128];   // Bs[k][n]

    const int tid = threadIdx.x;
    const int tx = tid & 15;        // 0..15 -> n micro
    const int ty = tid >> 4;        // 0..15 -> m micro
    const int bx = blockIdx.x;      // n tile
    const int by = blockIdx.y;      // m tile

    const float* Ap = (MODE == 1) ? g_vals : A;

    float acc[8][8];
#pragma unroll
    for (int i = 0; i < 8; i++)
#pragma unroll
        for (int j = 0; j < 8; j++) acc[i][j] = 0.0f;

    const int arow = tid >> 2;           // 0..63
    const int acol = (tid & 3) << 2;     // 0,4,8,12
    const int brow = tid >> 5;           // 0..7
    const int bcol = (tid & 31) << 2;    // 0..124

    for (int kb = 0; kb < K; kb += 16) {
        // load A tile (128 x 16), store transposed
#pragma unroll
        for (int r = 0; r < 2; r++) {
            int row = arow + r * 64;
            float4 a = *(const float4*)(Ap + (size_t)(by * 128 + row) * K + kb + acol);
            As[acol + 0][row] = a.x;
            As[acol + 1][row] = a.y;
            As[acol + 2][row] = a.z;
            As[acol + 3][row] = a.w;
        }
        // load B tile (16 x 128)
#pragma unroll
        for (int r = 0; r < 2; r++) {
            int row = brow + r * 8;
            *(float4*)&Bs[row][bcol] =
                *(const float4*)(Bm + (size_t)(kb + row) * N + bx * 128 + bcol);
        }
        __syncthreads();

#pragma unroll
        for (int k = 0; k < 16; k++) {
            float4 a0 = *(const float4*)&As[k][ty * 8];
            float4 a1 = *(const float4*)&As[k][ty * 8 + 4];
            float4 b0 = *(const float4*)&Bs[k][tx * 8];
            float4 b1 = *(const float4*)&Bs[k][tx * 8 + 4];
            float av[8] = {a0.x, a0.y, a0.z, a0.w, a1.x, a1.y, a1.z, a1.w};
            float bv[8] = {b0.x, b0.y, b0.z, b0.w, b1.x, b1.y, b1.z, b1.w};
#pragma unroll
            for (int i = 0; i < 8; i++)
#pragma unroll
                for (int j = 0; j < 8; j++)
                    acc[i][j] = fmaf(av[i], bv[j], acc[i][j]);
        }
        __syncthreads();
    }

    if (MODE == 0) {
        // scatter into g_qkv: n -> (which, h, hd); m -> (b, s)
#pragma unroll
        for (int i = 0; i < 8; i++) {
            int m = by * 128 + ty * 8 + i;
            int b = m >> 11;          // /2048
            int s = m & 2047;
#pragma unroll
            for (int j = 0; j < 8; j++) {
                int n = bx * 128 + tx * 8 + j;
                float v = acc[i][j] + bias[n];
                int which = n >> 10;
                int d = n & 1023;
                int h = d >> 6;
                int hd = d & 63;
                g_qkv[((((which * B_ + b) * H_ + h) * S_) + s) * HD_ + hd] = v;
            }
        }
    } else {
#pragma unroll
        for (int i = 0; i < 8; i++) {
            int m = by * 128 + ty * 8 + i;
#pragma unroll
            for (int jj = 0; jj < 2; jj++) {
                int n = bx * 128 + tx * 8 + jj * 4;
                float4 v;
                v.x = acc[i][jj * 4 + 0] + bias[n + 0];
                v.y = acc[i][jj * 4 + 1] + bias[n + 1];
                v.z = acc[i][jj * 4 + 2] + bias[n + 2];
                v.w = acc[i][jj * 4 + 3] + bias[n + 3];
                *(float4*)(C + (size_t)m * N + n) = v;
            }
        }
    }
}

// ---------------------------------------------------------------------------
// Flash attention: one CTA per (b, h, 64-query tile). 256 threads.
// Thread grid 16x16: ty -> 4 query rows, tx -> 4 key cols / 4 hd cols.
// smem: Qt[hd][q], Kt[hd][k] (transposed, outer-product GEMM1),
//       Vs[k][hd], Pt[k][q]. All pitch 68 floats (float4-aligned rows).
// ---------------------------------------------------------------------------
#define PITCH 68

__global__ void __launch_bounds__(256) attn_kernel(const float* __restrict__ mask)
{
    extern __shared__ float sm[];
    float* Qt = sm;                  // [64][PITCH]
    float* Kt = sm + 64 * PITCH;     // [64][PITCH]
    float* Vs = sm + 2 * 64 * PITCH; // [64][PITCH]
    float* Pt = sm + 3 * 64 * PITCH; // [64][PITCH]

    const int q0 = blockIdx.x * 64;
    const int h = blockIdx.y;
    const int b = blockIdx.z;
    const int tid = threadIdx.x;
    const int tx = tid & 15;
    const int ty = tid >> 4;

    const float* Qg = g_qkv + (((size_t)(0 * B_ + b) * H_ + h) * S_ + q0) * HD_;
    const float* Kg = g_qkv + (((size_t)(1 * B_ + b) * H_ + h) * S_) * HD_;
    const float* Vg = g_qkv + (((size_t)(2 * B_ + b) * H_ + h) * S_) * HD_;

    // Load Q tile, transposed to [hd][q]
#pragma unroll
    for (int r = 0; r < 4; r++) {
        int idx = tid + 256 * r;
        int q = idx >> 4;
        int c = (idx & 15) << 2;
        float4 v = *(const float4*)(Qg + q * HD_ + c);
        Qt[(c + 0) * PITCH + q] = v.x;
        Qt[(c + 1) * PITCH + q] = v.y;
        Qt[(c + 2) * PITCH + q] = v.z;
        Qt[(c + 3) * PITCH + q] = v.w;
    }

    float m_i[4], l_i[4], acc[4][4];
#pragma unroll
    for (int i = 0; i < 4; i++) {
        m_i[i] = -1e30f;
        l_i[i] = 0.0f;
#pragma unroll
        for (int j = 0; j < 4; j++) acc[i][j] = 0.0f;
    }

    const float scale = 0.125f;  // 1/sqrt(64)

    for (int k0 = 0; k0 < S_; k0 += 64) {
        // Load K (transposed) and V (natural) tiles
#pragma unroll
        for (int r = 0; r < 4; r++) {
            int idx = tid + 256 * r;
            int kk = idx >> 4;
            int c = (idx & 15) << 2;
            float4 kv = *(const float4*)(Kg + (size_t)(k0 + kk) * HD_ + c);
            Kt[(c + 0) * PITCH + kk] = kv.x;
            Kt[(c + 1) * PITCH + kk] = kv.y;
            Kt[(c + 2) * PITCH + kk] = kv.z;
            Kt[(c + 3) * PITCH + kk] = kv.w;
            float4 vv = *(const float4*)(Vg + (size_t)(k0 + kk) * HD_ + c);
            *(float4*)&Vs[kk * PITCH + c] = vv;
        }
        __syncthreads();

        // GEMM1: S[q][k] = sum_d Q[q][d] * K[k][d]  (outer product over d)
        float s[4][4];
#pragma unroll
        for (int i = 0; i < 4; i++)
#pragma unroll
            for (int j = 0; j < 4; j++) s[i][j] = 0.0f;

#pragma unroll
        for (int d = 0; d < 64; d++) {
            float4 qv = *(const float4*)&Qt[d * PITCH + ty * 4];
            float4 kv = *(const float4*)&Kt[d * PITCH + tx * 4];
            float qa[4] = {qv.x, qv.y, qv.z, qv.w};
            float ka[4] = {kv.x, kv.y, kv.z, kv.w};
#pragma unroll
            for (int i = 0; i < 4; i++)
#pragma unroll
                for (int j = 0; j < 4; j++)
                    s[i][j] = fmaf(qa[i], ka[j], s[i][j]);
        }

        // mask + scale + online softmax per query row
#pragma unroll
        for (int i = 0; i < 4; i++) {
            int q = q0 + ty * 4 + i;
            float4 mk = *(const float4*)(mask + ((size_t)b * S_ + q) * S_ + k0 + tx * 4);
            s[i][0] = s[i][0] * scale + mk.x * (-1e9f);
            s[i][1] = s[i][1] * scale + mk.y * (-1e9f);
            s[i][2] = s[i][2] * scale + mk.z * (-1e9f);
            s[i][3] = s[i][3] * scale + mk.w * (-1e9f);

            float mx = fmaxf(fmaxf(s[i][0], s[i][1]), fmaxf(s[i][2], s[i][3]));
#pragma unroll
            for (int o = 1; o < 16; o <<= 1)
                mx = fmaxf(mx, __shfl_xor_sync(0xffffffffu, mx, o));

            float mnew = fmaxf(m_i[i], mx);
            float corr = __expf(m_i[i] - mnew);
            float psum = 0.0f;
#pragma unroll
            for (int j = 0; j < 4; j++) {
                s[i][j] = __expf(s[i][j] - mnew);
                psum += s[i][j];
            }
#pragma unroll
            for (int o = 1; o < 16; o <<= 1)
                psum += __shfl_xor_sync(0xffffffffu, psum, o);

            l_i[i] = l_i[i] * corr + psum;
            m_i[i] = mnew;
#pragma unroll
            for (int j = 0; j < 4; j++) acc[i][j] *= corr;

            // write P transposed: Pt[k][q]
#pragma unroll
            for (int j = 0; j < 4; j++)
                Pt[(tx * 4 + j) * PITCH + ty * 4 + i] = s[i][j];
        }
        __syncthreads();

        // GEMM2: O[q][hd] += sum_k P[q][k] * V[k][hd]  (outer product over k)
#pragma unroll
        for (int kk = 0; kk < 64; kk++) {
            float4 pv = *(const float4*)&Pt[kk * PITCH + ty * 4];
            float4 vv = *(const float4*)&Vs[kk * PITCH + tx * 4];
            float pa[4] = {pv.x, pv.y, pv.z, pv.w};
            float va[4] = {vv.x, vv.y, vv.z, vv.w};
#pragma unroll
            for (int i = 0; i < 4; i++)
#pragma unroll
                for (int j = 0; j < 4; j++)
                    acc[i][j] = fmaf(pa[i], va[j], acc[i][j]);
        }
        __syncthreads();
    }

    // Epilogue: normalize, write scrambled layout
    // L = ((h*B + b)*S + q)*64 + hd   (faithful to reference's transpose+reshape)
#pragma unroll
    for (int i = 0; i < 4; i++) {
        float inv = 1.0f / l_i[i];
        int q = q0 + ty * 4 + i;
        float4 v;
        v.x = acc[i][0] * inv;
        v.y = acc[i][1] * inv;
        v.z = acc[i][2] * inv;
        v.w = acc[i][3] * inv;
        *(float4*)(g_vals + (((size_t)h * B_ + b) * S_ + q) * HD_ + tx * 4) = v;
    }
}

// ---------------------------------------------------------------------------
extern "C" void kernel_launch(void* const* d_in, const int* in_sizes, int n_in,
                              void* d_out, int out_size)
{
    const float* x    = (const float*)d_in[0];
    const float* mask = (const float*)d_in[1];
    const float* Wqkv = (const float*)d_in[2];
    const float* bqkv = (const float*)d_in[3];
    const float* Wo   = (const float*)d_in[4];
    const float* bo   = (const float*)d_in[5];
    float* out = (float*)d_out;

    const int M = B_ * S_;  // 4096

    // 1) QKV GEMM (scatter epilogue into g_qkv)
    gemm128<0><<<dim3(3 * D_ / 128, M / 128), 256>>>(x, Wqkv, bqkv, nullptr,
                                                     M, 3 * D_, D_);

    // 2) Flash attention
    int smem = 4 * 64 * PITCH * (int)sizeof(float);  // 69632 B
    cudaFuncSetAttribute(attn_kernel, cudaFuncAttributeMaxDynamicSharedMemorySize, smem);
    attn_kernel<<<dim3(S_ / 64, H_, B_), 256, smem>>>(mask);

    // 3) Output projection
    gemm128<1><<<dim3(D_ / 128, M / 128), 256>>>(nullptr, Wo, bo, out,
                                                 M, D_, D_);
}

// round 4
// speedup vs baseline: 1.5068x; 1.5068x over previous
#include <cuda_runtime.h>
#include <cstdint>

#define B_ 2
#define S_ 2048
#define D_ 1024
#define H_ 16
#define HD_ 64
#define M_   (B_ * S_)
#define N3_  (3 * D_)

__device__ float g_qkv[M_ * N3_];    // QKV out, row-major [4096][3072]
__device__ float g_vals[M_ * D_];    // scrambled attn output
__device__ float g_wtq[N3_ * D_];    // Wqkv^T [3072][1024]
__device__ float g_wto[D_ * D_];     // Wo^T   [1024][1024]

// ---------------- weight transpose: dst[n][k] = src[k][n] ----------------
__global__ void __launch_bounds__(256) transpose_k(
    const float* __restrict__ src, float* __restrict__ dst, int K, int N)
{
    __shared__ float t[32][33];
    int n0 = blockIdx.x * 32, k0 = blockIdx.y * 32;
    int tx = threadIdx.x, ty = threadIdx.y;
    for (int i = ty; i < 32; i += 8)
        t[i][tx] = src[(size_t)(k0 + i) * N + n0 + tx];
    __syncthreads();
    for (int i = ty; i < 32; i += 8)
        dst[(size_t)(n0 + i) * K + k0 + tx] = t[tx][i];
}

// ---------------- tf32 mma.sync GEMM: C = A[M,K] @ Bt[N,K]^T + bias ------
// Tile 128x128, BK=32. 256 threads = 8 warps (2m x 4n), warp = 64x32.
// Both A and Bt are K-major; smem layout [row][k] with PAD=36 (frag loads
// conflict-free: bank = 4*group + tig).
#define BM 128
#define BN 128
#define BK 32
#define PAD 36
#define TBUF (BM * PAD + BN * PAD)          // floats per buffer
#define GSM  (2 * TBUF * 4)                 // 73728 bytes

__device__ __forceinline__ uint32_t cvt_tf32(float f) {
    uint32_t u;
    asm("cvt.rna.tf32.f32 %0, %1;" : "=r"(u) : "f"(f));
    return u;
}

__device__ __forceinline__ void mma_tf32(float* c, const uint32_t* a, const uint32_t* b) {
    asm volatile(
        "mma.sync.aligned.m16n8k8.row.col.f32.tf32.tf32.f32 "
        "{%0,%1,%2,%3}, {%4,%5,%6,%7}, {%8,%9}, {%0,%1,%2,%3};"
        : "+f"(c[0]), "+f"(c[1]), "+f"(c[2]), "+f"(c[3])
        : "r"(a[0]), "r"(a[1]), "r"(a[2]), "r"(a[3]), "r"(b[0]), "r"(b[1]));
}

__global__ void __launch_bounds__(256) gemm_mma(
    const float* __restrict__ A, const float* __restrict__ Bt,
    const float* __restrict__ bias, float* __restrict__ C, int N, int K)
{
    extern __shared__ float smf[];
    uint32_t* sm = (uint32_t*)smf;   // tf32 bit patterns

    const int tid = threadIdx.x, wid = tid >> 5, lane = tid & 31;
    const int g = lane >> 2, t = lane & 3;
    const int wm = wid & 1, wn = wid >> 1;           // 2 x 4 warp grid
    const int m0 = blockIdx.y * BM, n0 = blockIdx.x * BN;

    const int ldr = tid >> 3;            // 0..31
    const int ldc = (tid & 7) << 2;      // 0,4,...,28

    const float* Ag = A + (size_t)m0 * K;
    const float* Bg = Bt + (size_t)n0 * K;

    float acc[4][4][4];
#pragma unroll
    for (int i = 0; i < 4; i++)
#pragma unroll
        for (int j = 0; j < 4; j++)
#pragma unroll
            for (int r = 0; r < 4; r++) acc[i][j][r] = 0.0f;

    const int KT = K / BK;   // 32 for K=1024
    float4 va[4], vb[4];

    // prologue: load kb=0 into regs, store to buf0
#pragma unroll
    for (int i = 0; i < 4; i++) {
        va[i] = *(const float4*)(Ag + (size_t)(ldr + i * 32) * K + ldc);
        vb[i] = *(const float4*)(Bg + (size_t)(ldr + i * 32) * K + ldc);
    }
    {
        uint32_t* As = sm;
        uint32_t* Bs = sm + BM * PAD;
#pragma unroll
        for (int i = 0; i < 4; i++) {
            int r = ldr + i * 32;
            uint4 ua = {cvt_tf32(va[i].x), cvt_tf32(va[i].y), cvt_tf32(va[i].z), cvt_tf32(va[i].w)};
            *(uint4*)&As[r * PAD + ldc] = ua;
            uint4 ub = {cvt_tf32(vb[i].x), cvt_tf32(vb[i].y), cvt_tf32(vb[i].z), cvt_tf32(vb[i].w)};
            *(uint4*)&Bs[r * PAD + ldc] = ub;
        }
    }
    __syncthreads();

    for (int kb = 0; kb < KT; kb++) {
        const int cur = kb & 1;
        const uint32_t* As = sm + cur * TBUF;
        const uint32_t* Bs = sm + cur * TBUF + BM * PAD;

        // prefetch next tile into registers
        if (kb + 1 < KT) {
            const float* An = Ag + (size_t)(kb + 1) * BK;
            const float* Bn = Bg + (size_t)(kb + 1) * BK;
#pragma unroll
            for (int i = 0; i < 4; i++) {
                va[i] = *(const float4*)(An + (size_t)(ldr + i * 32) * K + ldc);
                vb[i] = *(const float4*)(Bn + (size_t)(ldr + i * 32) * K + ldc);
            }
        }

        // compute: 4 k-steps of 8
#pragma unroll
        for (int ks = 0; ks < 4; ks++) {
            uint32_t af[4][4], bf[4][2];
#pragma unroll
            for (int mt = 0; mt < 4; mt++) {
                int row = wm * 64 + mt * 16;
                int kc = ks * 8 + t;
                af[mt][0] = As[(row + g) * PAD + kc];
                af[mt][1] = As[(row + g + 8) * PAD + kc];
                af[mt][2] = As[(row + g) * PAD + kc + 4];
                af[mt][3] = As[(row + g + 8) * PAD + kc + 4];
            }
#pragma unroll
            for (int nt = 0; nt < 4; nt++) {
                int col = wn * 32 + nt * 8;
                int kc = ks * 8 + t;
                bf[nt][0] = Bs[(col + g) * PAD + kc];
                bf[nt][1] = Bs[(col + g) * PAD + kc + 4];
            }
#pragma unroll
            for (int mt = 0; mt < 4; mt++)
#pragma unroll
                for (int nt = 0; nt < 4; nt++)
                    mma_tf32(acc[mt][nt], af[mt], bf[nt]);
        }

        // store prefetched tile into the other buffer
        if (kb + 1 < KT) {
            uint32_t* Asn = sm + (cur ^ 1) * TBUF;
            uint32_t* Bsn = sm + (cur ^ 1) * TBUF + BM * PAD;
#pragma unroll
            for (int i = 0; i < 4; i++) {
                int r = ldr + i * 32;
                uint4 ua = {cvt_tf32(va[i].x), cvt_tf32(va[i].y), cvt_tf32(va[i].z), cvt_tf32(va[i].w)};
                *(uint4*)&Asn[r * PAD + ldc] = ua;
                uint4 ub = {cvt_tf32(vb[i].x), cvt_tf32(vb[i].y), cvt_tf32(vb[i].z), cvt_tf32(vb[i].w)};
                *(uint4*)&Bsn[r * PAD + ldc] = ub;
            }
        }
        __syncthreads();
    }

    // epilogue: c0,c1 = (row+g, col+2t, col+2t+1); c2,c3 = row+g+8
#pragma unroll
    for (int mt = 0; mt < 4; mt++) {
        int row = m0 + wm * 64 + mt * 16 + g;
#pragma unroll
        for (int nt = 0; nt < 4; nt++) {
            int col = n0 + wn * 32 + nt * 8 + 2 * t;
            float bx = bias[col], by = bias[col + 1];
            float2 v0 = {acc[mt][nt][0] + bx, acc[mt][nt][1] + by};
            float2 v1 = {acc[mt][nt][2] + bx, acc[mt][nt][3] + by};
            *(float2*)(C + (size_t)row * N + col) = v0;
            *(float2*)(C + (size_t)(row + 8) * N + col) = v1;
        }
    }
}

// ---------------- flash attention (unchanged passing R1 kernel) ----------
#define PITCH 68

__global__ void __launch_bounds__(256) attn_kernel(const float* __restrict__ mask)
{
    extern __shared__ float sm[];
    float* Qt = sm;
    float* Kt = sm + 64 * PITCH;
    float* Vs = sm + 2 * 64 * PITCH;
    float* Pt = sm + 3 * 64 * PITCH;

    const int q0 = blockIdx.x * 64;
    const int h = blockIdx.y;
    const int b = blockIdx.z;
    const int tid = threadIdx.x;
    const int tx = tid & 15;
    const int ty = tid >> 4;

    const float* Qg = g_qkv + ((size_t)(b * S_ + q0)) * N3_ + h * HD_;
    const float* Kg = g_qkv + ((size_t)(b * S_)) * N3_ + D_ + h * HD_;
    const float* Vg = g_qkv + ((size_t)(b * S_)) * N3_ + 2 * D_ + h * HD_;

#pragma unroll
    for (int r = 0; r < 4; r++) {
        int idx = tid + 256 * r;
        int q = idx >> 4, c = (idx & 15) << 2;
        float4 v = *(const float4*)(Qg + (size_t)q * N3_ + c);
        Qt[(c + 0) * PITCH + q] = v.x;
        Qt[(c + 1) * PITCH + q] = v.y;
        Qt[(c + 2) * PITCH + q] = v.z;
        Qt[(c + 3) * PITCH + q] = v.w;
    }

    float m_i[4], l_i[4], acc[4][4];
#pragma unroll
    for (int i = 0; i < 4; i++) {
        m_i[i] = -1e30f; l_i[i] = 0.0f;
#pragma unroll
        for (int j = 0; j < 4; j++) acc[i][j] = 0.0f;
    }
    const float scale = 0.125f;

    for (int k0 = 0; k0 < S_; k0 += 64) {
#pragma unroll
        for (int r = 0; r < 4; r++) {
            int idx = tid + 256 * r;
            int kk = idx >> 4, c = (idx & 15) << 2;
            float4 kv = *(const float4*)(Kg + (size_t)(k0 + kk) * N3_ + c);
            Kt[(c + 0) * PITCH + kk] = kv.x;
            Kt[(c + 1) * PITCH + kk] = kv.y;
            Kt[(c + 2) * PITCH + kk] = kv.z;
            Kt[(c + 3) * PITCH + kk] = kv.w;
            float4 vv = *(const float4*)(Vg + (size_t)(k0 + kk) * N3_ + c);
            *(float4*)&Vs[kk * PITCH + c] = vv;
        }
        __syncthreads();

        float s[4][4];
#pragma unroll
        for (int i = 0; i < 4; i++)
#pragma unroll
            for (int j = 0; j < 4; j++) s[i][j] = 0.0f;

#pragma unroll
        for (int d = 0; d < 64; d++) {
            float4 qv = *(const float4*)&Qt[d * PITCH + ty * 4];
            float4 kv = *(const float4*)&Kt[d * PITCH + tx * 4];
            float qa[4] = {qv.x, qv.y, qv.z, qv.w};
            float ka[4] = {kv.x, kv.y, kv.z, kv.w};
#pragma unroll
            for (int i = 0; i < 4; i++)
#pragma unroll
                for (int j = 0; j < 4; j++)
                    s[i][j] = fmaf(qa[i], ka[j], s[i][j]);
        }

#pragma unroll
        for (int i = 0; i < 4; i++) {
            int q = q0 + ty * 4 + i;
            float4 mk = *(const float4*)(mask + ((size_t)b * S_ + q) * S_ + k0 + tx * 4);
            s[i][0] = s[i][0] * scale + mk.x * (-1e9f);
            s[i][1] = s[i][1] * scale + mk.y * (-1e9f);
            s[i][2] = s[i][2] * scale + mk.z * (-1e9f);
            s[i][3] = s[i][3] * scale + mk.w * (-1e9f);

            float mx = fmaxf(fmaxf(s[i][0], s[i][1]), fmaxf(s[i][2], s[i][3]));
#pragma unroll
            for (int o = 1; o < 16; o <<= 1)
                mx = fmaxf(mx, __shfl_xor_sync(0xffffffffu, mx, o));

            float mnew = fmaxf(m_i[i], mx);
            float corr = __expf(m_i[i] - mnew);
            float psum = 0.0f;
#pragma unroll
            for (int j = 0; j < 4; j++) { s[i][j] = __expf(s[i][j] - mnew); psum += s[i][j]; }
#pragma unroll
            for (int o = 1; o < 16; o <<= 1)
                psum += __shfl_xor_sync(0xffffffffu, psum, o);

            l_i[i] = l_i[i] * corr + psum;
            m_i[i] = mnew;
#pragma unroll
            for (int j = 0; j < 4; j++) acc[i][j] *= corr;
#pragma unroll
            for (int j = 0; j < 4; j++)
                Pt[(tx * 4 + j) * PITCH + ty * 4 + i] = s[i][j];
        }
        __syncthreads();

#pragma unroll
        for (int kk = 0; kk < 64; kk++) {
            float4 pv = *(const float4*)&Pt[kk * PITCH + ty * 4];
            float4 vv = *(const float4*)&Vs[kk * PITCH + tx * 4];
            float pa[4] = {pv.x, pv.y, pv.z, pv.w};
            float va[4] = {vv.x, vv.y, vv.z, vv.w};
#pragma unroll
            for (int i = 0; i < 4; i++)
#pragma unroll
                for (int j = 0; j < 4; j++)
                    acc[i][j] = fmaf(pa[i], va[j], acc[i][j]);
        }
        __syncthreads();
    }

#pragma unroll
    for (int i = 0; i < 4; i++) {
        float inv = 1.0f / l_i[i];
        int q = q0 + ty * 4 + i;
        float4 v;
        v.x = acc[i][0] * inv; v.y = acc[i][1] * inv;
        v.z = acc[i][2] * inv; v.w = acc[i][3] * inv;
        *(float4*)(g_vals + (((size_t)h * B_ + b) * S_ + q) * HD_ + tx * 4) = v;
    }
}

// ---------------------------------------------------------------------------
extern "C" void kernel_launch(void* const* d_in, const int* in_sizes, int n_in,
                              void* d_out, int out_size)
{
    const float* x    = (const float*)d_in[0];
    const float* mask = (const float*)d_in[1];
    const float* Wqkv = (const float*)d_in[2];
    const float* bqkv = (const float*)d_in[3];
    const float* Wo   = (const float*)d_in[4];
    const float* bo   = (const float*)d_in[5];
    float* out = (float*)d_out;

    void *p_qkv, *p_vals, *p_wtq, *p_wto;
    cudaGetSymbolAddress(&p_qkv, g_qkv);
    cudaGetSymbolAddress(&p_vals, g_vals);
    cudaGetSymbolAddress(&p_wtq, g_wtq);
    cudaGetSymbolAddress(&p_wto, g_wto);

    cudaFuncSetAttribute(gemm_mma, cudaFuncAttributeMaxDynamicSharedMemorySize, GSM);

    // 0) weights -> K-major
    transpose_k<<<dim3(N3_ / 32, D_ / 32), dim3(32, 8)>>>(Wqkv, (float*)p_wtq, D_, N3_);
    transpose_k<<<dim3(D_ / 32, D_ / 32), dim3(32, 8)>>>(Wo, (float*)p_wto, D_, D_);

    // 1) QKV GEMM (tf32 mma.sync)
    gemm_mma<<<dim3(N3_ / BN, M_ / BM), 256, GSM>>>(
        x, (const float*)p_wtq, bqkv, (float*)p_qkv, N3_, D_);

    // 2) flash attention
    int smem = 4 * 64 * PITCH * (int)sizeof(float);
    cudaFuncSetAttribute(attn_kernel, cudaFuncAttributeMaxDynamicSharedMemorySize, smem);
    attn_kernel<<<dim3(S_ / 64, H_, B_), 256, smem>>>(mask);

    // 3) output projection (tf32 mma.sync)
    gemm_mma<<<dim3(D_ / BN, M_ / BM), 256, GSM>>>(
        (const float*)p_vals, (const float*)p_wto, bo, out, D_, D_);
}

// round 5
// speedup vs baseline: 2.7686x; 1.8375x over previous
#include <cuda_runtime.h>
#include <cstdint>

#define B_ 2
#define S_ 2048
#define D_ 1024
#define H_ 16
#define HD_ 64
#define M_   (B_ * S_)
#define N3_  (3 * D_)

__device__ float g_qkv[M_ * N3_];
__device__ float g_vals[M_ * D_];
__device__ float g_wtq[N3_ * D_];
__device__ float g_wto[D_ * D_];

__device__ __forceinline__ uint32_t cvt_tf32(float f) {
    uint32_t u;
    asm("cvt.rna.tf32.f32 %0, %1;" : "=r"(u) : "f"(f));
    return u;
}
__device__ __forceinline__ void mma_tf32(float* c, const uint32_t* a, const uint32_t* b) {
    asm volatile(
        "mma.sync.aligned.m16n8k8.row.col.f32.tf32.tf32.f32 "
        "{%0,%1,%2,%3}, {%4,%5,%6,%7}, {%8,%9}, {%0,%1,%2,%3};"
        : "+f"(c[0]), "+f"(c[1]), "+f"(c[2]), "+f"(c[3])
        : "r"(a[0]), "r"(a[1]), "r"(a[2]), "r"(a[3]), "r"(b[0]), "r"(b[1]));
}

// ---------------- weight transpose ----------------
__global__ void __launch_bounds__(256) transpose_k(
    const float* __restrict__ src, float* __restrict__ dst, int K, int N)
{
    __shared__ float t[32][33];
    int n0 = blockIdx.x * 32, k0 = blockIdx.y * 32;
    int tx = threadIdx.x, ty = threadIdx.y;
    for (int i = ty; i < 32; i += 8)
        t[i][tx] = src[(size_t)(k0 + i) * N + n0 + tx];
    __syncthreads();
    for (int i = ty; i < 32; i += 8)
        dst[(size_t)(n0 + i) * K + k0 + tx] = t[tx][i];
}

// ---------------- tf32 mma GEMM (unchanged from passing R4) ----------------
#define BM 128
#define BN 128
#define BK 32
#define PAD 36
#define TBUF (BM * PAD + BN * PAD)
#define GSM  (2 * TBUF * 4)

__global__ void __launch_bounds__(256) gemm_mma(
    const float* __restrict__ A, const float* __restrict__ Bt,
    const float* __restrict__ bias, float* __restrict__ C, int N, int K)
{
    extern __shared__ float smf[];
    uint32_t* sm = (uint32_t*)smf;

    const int tid = threadIdx.x, wid = tid >> 5, lane = tid & 31;
    const int g = lane >> 2, t = lane & 3;
    const int wm = wid & 1, wn = wid >> 1;
    const int m0 = blockIdx.y * BM, n0 = blockIdx.x * BN;
    const int ldr = tid >> 3, ldc = (tid & 7) << 2;

    const float* Ag = A + (size_t)m0 * K;
    const float* Bg = Bt + (size_t)n0 * K;

    float acc[4][4][4];
#pragma unroll
    for (int i = 0; i < 4; i++)
#pragma unroll
        for (int j = 0; j < 4; j++)
#pragma unroll
            for (int r = 0; r < 4; r++) acc[i][j][r] = 0.0f;

    const int KT = K / BK;
    float4 va[4], vb[4];

#pragma unroll
    for (int i = 0; i < 4; i++) {
        va[i] = *(const float4*)(Ag + (size_t)(ldr + i * 32) * K + ldc);
        vb[i] = *(const float4*)(Bg + (size_t)(ldr + i * 32) * K + ldc);
    }
    {
        uint32_t* As = sm;
        uint32_t* Bs = sm + BM * PAD;
#pragma unroll
        for (int i = 0; i < 4; i++) {
            int r = ldr + i * 32;
            uint4 ua = {cvt_tf32(va[i].x), cvt_tf32(va[i].y), cvt_tf32(va[i].z), cvt_tf32(va[i].w)};
            *(uint4*)&As[r * PAD + ldc] = ua;
            uint4 ub = {cvt_tf32(vb[i].x), cvt_tf32(vb[i].y), cvt_tf32(vb[i].z), cvt_tf32(vb[i].w)};
            *(uint4*)&Bs[r * PAD + ldc] = ub;
        }
    }
    __syncthreads();

    for (int kb = 0; kb < KT; kb++) {
        const int cur = kb & 1;
        const uint32_t* As = sm + cur * TBUF;
        const uint32_t* Bs = sm + cur * TBUF + BM * PAD;

        if (kb + 1 < KT) {
            const float* An = Ag + (size_t)(kb + 1) * BK;
            const float* Bn = Bg + (size_t)(kb + 1) * BK;
#pragma unroll
            for (int i = 0; i < 4; i++) {
                va[i] = *(const float4*)(An + (size_t)(ldr + i * 32) * K + ldc);
                vb[i] = *(const float4*)(Bn + (size_t)(ldr + i * 32) * K + ldc);
            }
        }

#pragma unroll
        for (int ks = 0; ks < 4; ks++) {
            uint32_t af[4][4], bf[4][2];
#pragma unroll
            for (int mt = 0; mt < 4; mt++) {
                int row = wm * 64 + mt * 16;
                int kc = ks * 8 + t;
                af[mt][0] = As[(row + g) * PAD + kc];
                af[mt][1] = As[(row + g + 8) * PAD + kc];
                af[mt][2] = As[(row + g) * PAD + kc + 4];
                af[mt][3] = As[(row + g + 8) * PAD + kc + 4];
            }
#pragma unroll
            for (int nt = 0; nt < 4; nt++) {
                int col = wn * 32 + nt * 8;
                int kc = ks * 8 + t;
                bf[nt][0] = Bs[(col + g) * PAD + kc];
                bf[nt][1] = Bs[(col + g) * PAD + kc + 4];
            }
#pragma unroll
            for (int mt = 0; mt < 4; mt++)
#pragma unroll
                for (int nt = 0; nt < 4; nt++)
                    mma_tf32(acc[mt][nt], af[mt], bf[nt]);
        }

        if (kb + 1 < KT) {
            uint32_t* Asn = sm + (cur ^ 1) * TBUF;
            uint32_t* Bsn = sm + (cur ^ 1) * TBUF + BM * PAD;
#pragma unroll
            for (int i = 0; i < 4; i++) {
                int r = ldr + i * 32;
                uint4 ua = {cvt_tf32(va[i].x), cvt_tf32(va[i].y), cvt_tf32(va[i].z), cvt_tf32(va[i].w)};
                *(uint4*)&Asn[r * PAD + ldc] = ua;
                uint4 ub = {cvt_tf32(vb[i].x), cvt_tf32(vb[i].y), cvt_tf32(vb[i].z), cvt_tf32(vb[i].w)};
                *(uint4*)&Bsn[r * PAD + ldc] = ub;
            }
        }
        __syncthreads();
    }

#pragma unroll
    for (int mt = 0; mt < 4; mt++) {
        int row = m0 + wm * 64 + mt * 16 + g;
#pragma unroll
        for (int nt = 0; nt < 4; nt++) {
            int col = n0 + wn * 32 + nt * 8 + 2 * t;
            float bx = bias[col], by = bias[col + 1];
            float2 v0 = {acc[mt][nt][0] + bx, acc[mt][nt][1] + by};
            float2 v1 = {acc[mt][nt][2] + bx, acc[mt][nt][3] + by};
            *(float2*)(C + (size_t)row * N + col) = v0;
            *(float2*)(C + (size_t)(row + 8) * N + col) = v1;
        }
    }
}

// ---------------- tensor-core flash attention ----------------
// CTA = (64 q-rows, h, b); 4 warps x 16 rows. Pitch 68 (== 4 mod 32):
// all mma fragment accesses hit bank 4g+t -> conflict-free.
#define AP 68
#define ASM (3 * 64 * AP * 4)   // Ks, Vt, Pt = 52224 B

__global__ void __launch_bounds__(128) attn_mma(const float* __restrict__ mask)
{
    extern __shared__ uint32_t sm[];
    uint32_t* Ks = sm;                 // [key][d]   tf32 bits
    uint32_t* Vt = sm + 64 * AP;       // [d][key]   tf32 bits
    uint32_t* Pt = sm + 2 * 64 * AP;   // [q][key]   tf32 bits (Q staging first)

    const int q0 = blockIdx.x * 64;
    const int h = blockIdx.y, b = blockIdx.z;
    const int tid = threadIdx.x, w = tid >> 5, lane = tid & 31;
    const int g = lane >> 2, t = lane & 3;
    const int r0 = w * 16 + g;         // local q row (and r0+8)

    const float* Qg = g_qkv + (size_t)(b * S_ + q0) * N3_ + h * HD_;
    const float* Kg = g_qkv + (size_t)(b * S_) * N3_ + D_ + h * HD_;
    const float* Vg = g_qkv + (size_t)(b * S_) * N3_ + 2 * D_ + h * HD_;

    // Stage Q (x 0.125) into Pt region as fp32, then pull fragments
    float* Qs = (float*)Pt;
#pragma unroll
    for (int i = 0; i < 8; i++) {
        int idx = tid + 128 * i;
        int r = idx >> 4, c = (idx & 15) << 2;
        float4 v = *(const float4*)(Qg + (size_t)r * N3_ + c);
        v.x *= 0.125f; v.y *= 0.125f; v.z *= 0.125f; v.w *= 0.125f;
        *(float4*)&Qs[r * AP + c] = v;
    }
    __syncthreads();

    uint32_t qf[8][4];
#pragma unroll
    for (int ks = 0; ks < 8; ks++) {
        int kc = ks * 8 + t;
        qf[ks][0] = cvt_tf32(Qs[r0 * AP + kc]);
        qf[ks][1] = cvt_tf32(Qs[(r0 + 8) * AP + kc]);
        qf[ks][2] = cvt_tf32(Qs[r0 * AP + kc + 4]);
        qf[ks][3] = cvt_tf32(Qs[(r0 + 8) * AP + kc + 4]);
    }
    __syncthreads();

    float m0 = -1e30f, m1 = -1e30f, l0 = 0.0f, l1 = 0.0f;
    float o[8][4];
#pragma unroll
    for (int nt = 0; nt < 8; nt++)
#pragma unroll
        for (int j = 0; j < 4; j++) o[nt][j] = 0.0f;

    const float* mrow0 = mask + ((size_t)b * S_ + q0 + r0) * S_ + 2 * t;
    const float* mrow1 = mrow0 + 8 * S_;

    for (int k0 = 0; k0 < S_; k0 += 64) {
        // load K -> Ks[key][d], V -> Vt[d][key] (both tf32 bits)
#pragma unroll
        for (int i = 0; i < 8; i++) {
            int idx = tid + 128 * i;
            int r = idx >> 4, c = (idx & 15) << 2;
            float4 kv = *(const float4*)(Kg + (size_t)(k0 + r) * N3_ + c);
            uint4 u = {cvt_tf32(kv.x), cvt_tf32(kv.y), cvt_tf32(kv.z), cvt_tf32(kv.w)};
            *(uint4*)&Ks[r * AP + c] = u;
            float4 vv = *(const float4*)(Vg + (size_t)(k0 + r) * N3_ + c);
            Vt[(c + 0) * AP + r] = cvt_tf32(vv.x);
            Vt[(c + 1) * AP + r] = cvt_tf32(vv.y);
            Vt[(c + 2) * AP + r] = cvt_tf32(vv.z);
            Vt[(c + 3) * AP + r] = cvt_tf32(vv.w);
        }
        __syncthreads();

        // GEMM1: scores = Qscaled @ K^T
        float s[8][4];
#pragma unroll
        for (int nt = 0; nt < 8; nt++)
#pragma unroll
            for (int j = 0; j < 4; j++) s[nt][j] = 0.0f;
#pragma unroll
        for (int ks = 0; ks < 8; ks++) {
            int kc = ks * 8 + t;
#pragma unroll
            for (int nt = 0; nt < 8; nt++) {
                uint32_t bf[2];
                bf[0] = Ks[(nt * 8 + g) * AP + kc];
                bf[1] = Ks[(nt * 8 + g) * AP + kc + 4];
                mma_tf32(s[nt], qf[ks], bf);
            }
        }

        // mask + online softmax (rows r0 and r0+8, all in registers)
        float mx0 = -1e30f, mx1 = -1e30f;
#pragma unroll
        for (int nt = 0; nt < 8; nt++) {
            float2 mk0 = *(const float2*)(mrow0 + k0 + nt * 8);
            float2 mk1 = *(const float2*)(mrow1 + k0 + nt * 8);
            s[nt][0] += mk0.x * (-1e9f);
            s[nt][1] += mk0.y * (-1e9f);
            s[nt][2] += mk1.x * (-1e9f);
            s[nt][3] += mk1.y * (-1e9f);
            mx0 = fmaxf(mx0, fmaxf(s[nt][0], s[nt][1]));
            mx1 = fmaxf(mx1, fmaxf(s[nt][2], s[nt][3]));
        }
        mx0 = fmaxf(mx0, __shfl_xor_sync(0xffffffffu, mx0, 1));
        mx0 = fmaxf(mx0, __shfl_xor_sync(0xffffffffu, mx0, 2));
        mx1 = fmaxf(mx1, __shfl_xor_sync(0xffffffffu, mx1, 1));
        mx1 = fmaxf(mx1, __shfl_xor_sync(0xffffffffu, mx1, 2));

        float mn0 = fmaxf(m0, mx0), mn1 = fmaxf(m1, mx1);
        float c0 = __expf(m0 - mn0), c1 = __expf(m1 - mn1);
        float ps0 = 0.0f, ps1 = 0.0f;
#pragma unroll
        for (int nt = 0; nt < 8; nt++) {
            s[nt][0] = __expf(s[nt][0] - mn0);
            s[nt][1] = __expf(s[nt][1] - mn0);
            s[nt][2] = __expf(s[nt][2] - mn1);
            s[nt][3] = __expf(s[nt][3] - mn1);
            ps0 += s[nt][0] + s[nt][1];
            ps1 += s[nt][2] + s[nt][3];
        }
        ps0 += __shfl_xor_sync(0xffffffffu, ps0, 1);
        ps0 += __shfl_xor_sync(0xffffffffu, ps0, 2);
        ps1 += __shfl_xor_sync(0xffffffffu, ps1, 1);
        ps1 += __shfl_xor_sync(0xffffffffu, ps1, 2);

        l0 = l0 * c0 + ps0; l1 = l1 * c1 + ps1;
        m0 = mn0; m1 = mn1;
#pragma unroll
        for (int nt = 0; nt < 8; nt++) {
            o[nt][0] *= c0; o[nt][1] *= c0;
            o[nt][2] *= c1; o[nt][3] *= c1;
            uint2 p0 = {cvt_tf32(s[nt][0]), cvt_tf32(s[nt][1])};
            uint2 p1 = {cvt_tf32(s[nt][2]), cvt_tf32(s[nt][3])};
            *(uint2*)&Pt[r0 * AP + nt * 8 + 2 * t] = p0;
            *(uint2*)&Pt[(r0 + 8) * AP + nt * 8 + 2 * t] = p1;
        }
        __syncthreads();

        // GEMM2: O += P @ V   (A-frags from Pt, B-frags from Vt)
#pragma unroll
        for (int ks = 0; ks < 8; ks++) {
            int kc = ks * 8 + t;
            uint32_t af[4];
            af[0] = Pt[r0 * AP + kc];
            af[1] = Pt[(r0 + 8) * AP + kc];
            af[2] = Pt[r0 * AP + kc + 4];
            af[3] = Pt[(r0 + 8) * AP + kc + 4];
#pragma unroll
            for (int nt = 0; nt < 8; nt++) {
                uint32_t bf[2];
                bf[0] = Vt[(nt * 8 + g) * AP + kc];
                bf[1] = Vt[(nt * 8 + g) * AP + kc + 4];
                mma_tf32(o[nt], af, bf);
            }
        }
        __syncthreads();
    }

    // epilogue: normalize + write scrambled layout (reference transpose+reshape)
    float i0 = 1.0f / l0, i1 = 1.0f / l1;
    float* Og0 = g_vals + (((size_t)h * B_ + b) * S_ + q0 + r0) * HD_;
    float* Og1 = Og0 + 8 * HD_;
#pragma unroll
    for (int nt = 0; nt < 8; nt++) {
        float2 v0 = {o[nt][0] * i0, o[nt][1] * i0};
        float2 v1 = {o[nt][2] * i1, o[nt][3] * i1};
        *(float2*)(Og0 + nt * 8 + 2 * t) = v0;
        *(float2*)(Og1 + nt * 8 + 2 * t) = v1;
    }
}

// ---------------------------------------------------------------------------
extern "C" void kernel_launch(void* const* d_in, const int* in_sizes, int n_in,
                              void* d_out, int out_size)
{
    const float* x    = (const float*)d_in[0];
    const float* mask = (const float*)d_in[1];
    const float* Wqkv = (const float*)d_in[2];
    const float* bqkv = (const float*)d_in[3];
    const float* Wo   = (const float*)d_in[4];
    const float* bo   = (const float*)d_in[5];
    float* out = (float*)d_out;

    void *p_qkv, *p_vals, *p_wtq, *p_wto;
    cudaGetSymbolAddress(&p_qkv, g_qkv);
    cudaGetSymbolAddress(&p_vals, g_vals);
    cudaGetSymbolAddress(&p_wtq, g_wtq);
    cudaGetSymbolAddress(&p_wto, g_wto);

    cudaFuncSetAttribute(gemm_mma, cudaFuncAttributeMaxDynamicSharedMemorySize, GSM);
    cudaFuncSetAttribute(attn_mma, cudaFuncAttributeMaxDynamicSharedMemorySize, ASM);

    transpose_k<<<dim3(N3_ / 32, D_ / 32), dim3(32, 8)>>>(Wqkv, (float*)p_wtq, D_, N3_);
    transpose_k<<<dim3(D_ / 32, D_ / 32), dim3(32, 8)>>>(Wo, (float*)p_wto, D_, D_);

    gemm_mma<<<dim3(N3_ / BN, M_ / BM), 256, GSM>>>(
        x, (const float*)p_wtq, bqkv, (float*)p_qkv, N3_, D_);

    attn_mma<<<dim3(S_ / 64, H_, B_), 128, ASM>>>(mask);

    gemm_mma<<<dim3(D_ / BN, M_ / BM), 256, GSM>>>(
        (const float*)p_vals, (const float*)p_wto, bo, out, D_, D_);
}

// round 6
// speedup vs baseline: 3.0846x; 1.1141x over previous
#include <cuda_runtime.h>
#include <cstdint>

#define B_ 2
#define S_ 2048
#define D_ 1024
#define H_ 16
#define HD_ 64
#define M_   (B_ * S_)
#define N3_  (3 * D_)

__device__ float g_qkv[M_ * N3_];
__device__ float g_vals[M_ * D_];
__device__ float g_wtq[N3_ * D_];
__device__ float g_wto[D_ * D_];

__device__ __forceinline__ uint32_t cvt_tf32(float f) {
    uint32_t u;
    asm("cvt.rna.tf32.f32 %0, %1;" : "=r"(u) : "f"(f));
    return u;
}
__device__ __forceinline__ void mma_tf32(float* c, const uint32_t* a, const uint32_t* b) {
    asm volatile(
        "mma.sync.aligned.m16n8k8.row.col.f32.tf32.tf32.f32 "
        "{%0,%1,%2,%3}, {%4,%5,%6,%7}, {%8,%9}, {%0,%1,%2,%3};"
        : "+f"(c[0]), "+f"(c[1]), "+f"(c[2]), "+f"(c[3])
        : "r"(a[0]), "r"(a[1]), "r"(a[2]), "r"(a[3]), "r"(b[0]), "r"(b[1]));
}

// ---------------- weight transpose ----------------
__global__ void __launch_bounds__(256) transpose_k(
    const float* __restrict__ src, float* __restrict__ dst, int K, int N)
{
    __shared__ float t[32][33];
    int n0 = blockIdx.x * 32, k0 = blockIdx.y * 32;
    int tx = threadIdx.x, ty = threadIdx.y;
    for (int i = ty; i < 32; i += 8)
        t[i][tx] = src[(size_t)(k0 + i) * N + n0 + tx];
    __syncthreads();
    for (int i = ty; i < 32; i += 8)
        dst[(size_t)(n0 + i) * K + k0 + tx] = t[tx][i];
}

// ---------------- tf32 mma GEMM (unchanged, passing) ----------------
#define BM 128
#define BN 128
#define BK 32
#define PAD 36
#define TBUF (BM * PAD + BN * PAD)
#define GSM  (2 * TBUF * 4)

__global__ void __launch_bounds__(256) gemm_mma(
    const float* __restrict__ A, const float* __restrict__ Bt,
    const float* __restrict__ bias, float* __restrict__ C, int N, int K)
{
    extern __shared__ float smf[];
    uint32_t* sm = (uint32_t*)smf;

    const int tid = threadIdx.x, wid = tid >> 5, lane = tid & 31;
    const int g = lane >> 2, t = lane & 3;
    const int wm = wid & 1, wn = wid >> 1;
    const int m0 = blockIdx.y * BM, n0 = blockIdx.x * BN;
    const int ldr = tid >> 3, ldc = (tid & 7) << 2;

    const float* Ag = A + (size_t)m0 * K;
    const float* Bg = Bt + (size_t)n0 * K;

    float acc[4][4][4];
#pragma unroll
    for (int i = 0; i < 4; i++)
#pragma unroll
        for (int j = 0; j < 4; j++)
#pragma unroll
            for (int r = 0; r < 4; r++) acc[i][j][r] = 0.0f;

    const int KT = K / BK;
    float4 va[4], vb[4];

#pragma unroll
    for (int i = 0; i < 4; i++) {
        va[i] = *(const float4*)(Ag + (size_t)(ldr + i * 32) * K + ldc);
        vb[i] = *(const float4*)(Bg + (size_t)(ldr + i * 32) * K + ldc);
    }
    {
        uint32_t* As = sm;
        uint32_t* Bs = sm + BM * PAD;
#pragma unroll
        for (int i = 0; i < 4; i++) {
            int r = ldr + i * 32;
            uint4 ua = {cvt_tf32(va[i].x), cvt_tf32(va[i].y), cvt_tf32(va[i].z), cvt_tf32(va[i].w)};
            *(uint4*)&As[r * PAD + ldc] = ua;
            uint4 ub = {cvt_tf32(vb[i].x), cvt_tf32(vb[i].y), cvt_tf32(vb[i].z), cvt_tf32(vb[i].w)};
            *(uint4*)&Bs[r * PAD + ldc] = ub;
        }
    }
    __syncthreads();

    for (int kb = 0; kb < KT; kb++) {
        const int cur = kb & 1;
        const uint32_t* As = sm + cur * TBUF;
        const uint32_t* Bs = sm + cur * TBUF + BM * PAD;

        if (kb + 1 < KT) {
            const float* An = Ag + (size_t)(kb + 1) * BK;
            const float* Bn = Bg + (size_t)(kb + 1) * BK;
#pragma unroll
            for (int i = 0; i < 4; i++) {
                va[i] = *(const float4*)(An + (size_t)(ldr + i * 32) * K + ldc);
                vb[i] = *(const float4*)(Bn + (size_t)(ldr + i * 32) * K + ldc);
            }
        }

#pragma unroll
        for (int ks = 0; ks < 4; ks++) {
            uint32_t af[4][4], bf[4][2];
#pragma unroll
            for (int mt = 0; mt < 4; mt++) {
                int row = wm * 64 + mt * 16;
                int kc = ks * 8 + t;
                af[mt][0] = As[(row + g) * PAD + kc];
                af[mt][1] = As[(row + g + 8) * PAD + kc];
                af[mt][2] = As[(row + g) * PAD + kc + 4];
                af[mt][3] = As[(row + g + 8) * PAD + kc + 4];
            }
#pragma unroll
            for (int nt = 0; nt < 4; nt++) {
                int col = wn * 32 + nt * 8;
                int kc = ks * 8 + t;
                bf[nt][0] = Bs[(col + g) * PAD + kc];
                bf[nt][1] = Bs[(col + g) * PAD + kc + 4];
            }
#pragma unroll
            for (int mt = 0; mt < 4; mt++)
#pragma unroll
                for (int nt = 0; nt < 4; nt++)
                    mma_tf32(acc[mt][nt], af[mt], bf[nt]);
        }

        if (kb + 1 < KT) {
            uint32_t* Asn = sm + (cur ^ 1) * TBUF;
            uint32_t* Bsn = sm + (cur ^ 1) * TBUF + BM * PAD;
#pragma unroll
            for (int i = 0; i < 4; i++) {
                int r = ldr + i * 32;
                uint4 ua = {cvt_tf32(va[i].x), cvt_tf32(va[i].y), cvt_tf32(va[i].z), cvt_tf32(va[i].w)};
                *(uint4*)&Asn[r * PAD + ldc] = ua;
                uint4 ub = {cvt_tf32(vb[i].x), cvt_tf32(vb[i].y), cvt_tf32(vb[i].z), cvt_tf32(vb[i].w)};
                *(uint4*)&Bsn[r * PAD + ldc] = ub;
            }
        }
        __syncthreads();
    }

#pragma unroll
    for (int mt = 0; mt < 4; mt++) {
        int row = m0 + wm * 64 + mt * 16 + g;
#pragma unroll
        for (int nt = 0; nt < 4; nt++) {
            int col = n0 + wn * 32 + nt * 8 + 2 * t;
            float bx = bias[col], by = bias[col + 1];
            float2 v0 = {acc[mt][nt][0] + bx, acc[mt][nt][1] + by};
            float2 v1 = {acc[mt][nt][2] + bx, acc[mt][nt][3] + by};
            *(float2*)(C + (size_t)row * N + col) = v0;
            *(float2*)(C + (size_t)(row + 8) * N + col) = v1;
        }
    }
}

// ---------------- tensor-core flash attention ----------------
#define AP 68
#define ASM (3 * 64 * AP * 4)

__global__ void __launch_bounds__(128) attn_mma(const float* __restrict__ mask)
{
    extern __shared__ uint32_t sm[];
    uint32_t* Ks = sm;                 // [key][d]
    uint32_t* Vt = sm + 64 * AP;       // [d][key]
    uint32_t* Pt = sm + 2 * 64 * AP;   // [q][key] (Q staging first)

    const int q0 = blockIdx.x * 64;
    const int h = blockIdx.y, b = blockIdx.z;
    const int tid = threadIdx.x, w = tid >> 5, lane = tid & 31;
    const int g = lane >> 2, t = lane & 3;
    const int r0 = w * 16 + g;

    const float* Qg = g_qkv + (size_t)(b * S_ + q0) * N3_ + h * HD_;
    const float* Kg = g_qkv + (size_t)(b * S_) * N3_ + D_ + h * HD_;
    const float* Vg = g_qkv + (size_t)(b * S_) * N3_ + 2 * D_ + h * HD_;

    // Stage Q (x 0.125), pull fragments into registers
    float* Qs = (float*)Pt;
#pragma unroll
    for (int i = 0; i < 8; i++) {
        int idx = tid + 128 * i;
        int r = idx >> 4, c = (idx & 15) << 2;
        float4 v = *(const float4*)(Qg + (size_t)r * N3_ + c);
        v.x *= 0.125f; v.y *= 0.125f; v.z *= 0.125f; v.w *= 0.125f;
        *(float4*)&Qs[r * AP + c] = v;
    }
    __syncthreads();

    uint32_t qf[8][4];
#pragma unroll
    for (int ks = 0; ks < 8; ks++) {
        int kc = ks * 8 + t;
        qf[ks][0] = cvt_tf32(Qs[r0 * AP + kc]);
        qf[ks][1] = cvt_tf32(Qs[(r0 + 8) * AP + kc]);
        qf[ks][2] = cvt_tf32(Qs[r0 * AP + kc + 4]);
        qf[ks][3] = cvt_tf32(Qs[(r0 + 8) * AP + kc + 4]);
    }
    __syncthreads();

    float m0 = -1e30f, m1 = -1e30f, l0 = 0.0f, l1 = 0.0f;
    float o[8][4];
#pragma unroll
    for (int nt = 0; nt < 8; nt++)
#pragma unroll
        for (int j = 0; j < 4; j++) o[nt][j] = 0.0f;

    const float* mrow0 = mask + ((size_t)b * S_ + q0 + r0) * S_ + 2 * t;
    const float* mrow1 = mrow0 + 8 * S_;

    // V loader mapping: thread = (hd column vc, key quad vr0)
    const int vc = tid & 63;
    const int vr0 = (tid >> 6) * 4;

    for (int k0 = 0; k0 < S_; k0 += 64) {
        // K -> Ks[key][d] (uint4 stores, conflict-free)
#pragma unroll
        for (int i = 0; i < 8; i++) {
            int idx = tid + 128 * i;
            int r = idx >> 4, c = (idx & 15) << 2;
            float4 kv = *(const float4*)(Kg + (size_t)(k0 + r) * N3_ + c);
            uint4 u = {cvt_tf32(kv.x), cvt_tf32(kv.y), cvt_tf32(kv.z), cvt_tf32(kv.w)};
            *(uint4*)&Ks[r * AP + c] = u;
        }
        // V -> Vt[d][key]: 4 keys per thread at one hd column, STS.128
        // conflict-free (addr stride 68 words -> 8-lane phase covers 32 banks)
#pragma unroll
        for (int i = 0; i < 8; i++) {
            int r = vr0 + i * 8;
            uint4 u;
            u.x = cvt_tf32(Vg[(size_t)(k0 + r + 0) * N3_ + vc]);
            u.y = cvt_tf32(Vg[(size_t)(k0 + r + 1) * N3_ + vc]);
            u.z = cvt_tf32(Vg[(size_t)(k0 + r + 2) * N3_ + vc]);
            u.w = cvt_tf32(Vg[(size_t)(k0 + r + 3) * N3_ + vc]);
            *(uint4*)&Vt[vc * AP + r] = u;
        }
        __syncthreads();

        // GEMM1: scores = Qscaled @ K^T
        float s[8][4];
#pragma unroll
        for (int nt = 0; nt < 8; nt++)
#pragma unroll
            for (int j = 0; j < 4; j++) s[nt][j] = 0.0f;
#pragma unroll
        for (int ks = 0; ks < 8; ks++) {
            int kc = ks * 8 + t;
#pragma unroll
            for (int nt = 0; nt < 8; nt++) {
                uint32_t bf[2];
                bf[0] = Ks[(nt * 8 + g) * AP + kc];
                bf[1] = Ks[(nt * 8 + g) * AP + kc + 4];
                mma_tf32(s[nt], qf[ks], bf);
            }
        }

        // mask + online softmax in registers
        float mx0 = -1e30f, mx1 = -1e30f;
#pragma unroll
        for (int nt = 0; nt < 8; nt++) {
            float2 mk0 = *(const float2*)(mrow0 + k0 + nt * 8);
            float2 mk1 = *(const float2*)(mrow1 + k0 + nt * 8);
            s[nt][0] += mk0.x * (-1e9f);
            s[nt][1] += mk0.y * (-1e9f);
            s[nt][2] += mk1.x * (-1e9f);
            s[nt][3] += mk1.y * (-1e9f);
            mx0 = fmaxf(mx0, fmaxf(s[nt][0], s[nt][1]));
            mx1 = fmaxf(mx1, fmaxf(s[nt][2], s[nt][3]));
        }
        mx0 = fmaxf(mx0, __shfl_xor_sync(0xffffffffu, mx0, 1));
        mx0 = fmaxf(mx0, __shfl_xor_sync(0xffffffffu, mx0, 2));
        mx1 = fmaxf(mx1, __shfl_xor_sync(0xffffffffu, mx1, 1));
        mx1 = fmaxf(mx1, __shfl_xor_sync(0xffffffffu, mx1, 2));

        float mn0 = fmaxf(m0, mx0), mn1 = fmaxf(m1, mx1);
        float c0 = __expf(m0 - mn0), c1 = __expf(m1 - mn1);
        float ps0 = 0.0f, ps1 = 0.0f;
#pragma unroll
        for (int nt = 0; nt < 8; nt++) {
            s[nt][0] = __expf(s[nt][0] - mn0);
            s[nt][1] = __expf(s[nt][1] - mn0);
            s[nt][2] = __expf(s[nt][2] - mn1);
            s[nt][3] = __expf(s[nt][3] - mn1);
            ps0 += s[nt][0] + s[nt][1];
            ps1 += s[nt][2] + s[nt][3];
        }
        ps0 += __shfl_xor_sync(0xffffffffu, ps0, 1);
        ps0 += __shfl_xor_sync(0xffffffffu, ps0, 2);
        ps1 += __shfl_xor_sync(0xffffffffu, ps1, 1);
        ps1 += __shfl_xor_sync(0xffffffffu, ps1, 2);

        l0 = l0 * c0 + ps0; l1 = l1 * c1 + ps1;
        m0 = mn0; m1 = mn1;
#pragma unroll
        for (int nt = 0; nt < 8; nt++) {
            o[nt][0] *= c0; o[nt][1] *= c0;
            o[nt][2] *= c1; o[nt][3] *= c1;
            uint2 p0 = {cvt_tf32(s[nt][0]), cvt_tf32(s[nt][1])};
            uint2 p1 = {cvt_tf32(s[nt][2]), cvt_tf32(s[nt][3])};
            *(uint2*)&Pt[r0 * AP + nt * 8 + 2 * t] = p0;
            *(uint2*)&Pt[(r0 + 8) * AP + nt * 8 + 2 * t] = p1;
        }
        __syncthreads();

        // GEMM2: O += P @ V
#pragma unroll
        for (int ks = 0; ks < 8; ks++) {
            int kc = ks * 8 + t;
            uint32_t af[4];
            af[0] = Pt[r0 * AP + kc];
            af[1] = Pt[(r0 + 8) * AP + kc];
            af[2] = Pt[r0 * AP + kc + 4];
            af[3] = Pt[(r0 + 8) * AP + kc + 4];
#pragma unroll
            for (int nt = 0; nt < 8; nt++) {
                uint32_t bf[2];
                bf[0] = Vt[(nt * 8 + g) * AP + kc];
                bf[1] = Vt[(nt * 8 + g) * AP + kc + 4];
                mma_tf32(o[nt], af, bf);
            }
        }
        __syncthreads();
    }

    float i0 = 1.0f / l0, i1 = 1.0f / l1;
    float* Og0 = g_vals + (((size_t)h * B_ + b) * S_ + q0 + r0) * HD_;
    float* Og1 = Og0 + 8 * HD_;
#pragma unroll
    for (int nt = 0; nt < 8; nt++) {
        float2 v0 = {o[nt][0] * i0, o[nt][1] * i0};
        float2 v1 = {o[nt][2] * i1, o[nt][3] * i1};
        *(float2*)(Og0 + nt * 8 + 2 * t) = v0;
        *(float2*)(Og1 + nt * 8 + 2 * t) = v1;
    }
}

// ---------------------------------------------------------------------------
extern "C" void kernel_launch(void* const* d_in, const int* in_sizes, int n_in,
                              void* d_out, int out_size)
{
    const float* x    = (const float*)d_in[0];
    const float* mask = (const float*)d_in[1];
    const float* Wqkv = (const float*)d_in[2];
    const float* bqkv = (const float*)d_in[3];
    const float* Wo   = (const float*)d_in[4];
    const float* bo   = (const float*)d_in[5];
    float* out = (float*)d_out;

    void *p_qkv, *p_vals, *p_wtq, *p_wto;
    cudaGetSymbolAddress(&p_qkv, g_qkv);
    cudaGetSymbolAddress(&p_vals, g_vals);
    cudaGetSymbolAddress(&p_wtq, g_wtq);
    cudaGetSymbolAddress(&p_wto, g_wto);

    cudaFuncSetAttribute(gemm_mma, cudaFuncAttributeMaxDynamicSharedMemorySize, GSM);
    cudaFuncSetAttribute(attn_mma, cudaFuncAttributeMaxDynamicSharedMemorySize, ASM);

    transpose_k<<<dim3(N3_ / 32, D_ / 32), dim3(32, 8)>>>(Wqkv, (float*)p_wtq, D_, N3_);
    transpose_k<<<dim3(D_ / 32, D_ / 32), dim3(32, 8)>>>(Wo, (float*)p_wto, D_, D_);

    gemm_mma<<<dim3(N3_ / BN, M_ / BM), 256, GSM>>>(
        x, (const float*)p_wtq, bqkv, (float*)p_qkv, N3_, D_);

    attn_mma<<<dim3(S_ / 64, H_, B_), 128, ASM>>>(mask);

    gemm_mma<<<dim3(D_ / BN, M_ / BM), 256, GSM>>>(
        (const float*)p_vals, (const float*)p_wto, bo, out, D_, D_);
}